// round 5
// baseline (speedup 1.0000x reference)
#include <cuda_runtime.h>
#include <math.h>

#define DIMD 512
#define HID  2048
#define NE   16
#define NB   8
#define NN   2048
#define CAP  256
#define NTOK (NB*NN)          // 16384
#define BC   (NB*CAP)         // 2048 rows per expert

// ---------------- device scratch (no allocations allowed) ----------------
__device__ float          g_weights[NTOK*NE];   // renormalized gate weights (expert order)
__device__ unsigned char  g_mask[NTOK*NE];      // selection mask (post-capacity after scan)
__device__ int            g_posE[NTOK*NE];      // pos_e * mask
__device__ int            g_postok[NTOK];       // sum_e posE
__device__ float          g_proxy[NB*NE];       // sum_n raw probs
__device__ float          g_density[NB*NE];     // mean_n mask
__device__ float          g_ei[(size_t)NE*BC*DIMD];    // 64 MB expert inputs
__device__ float          g_hidden[(size_t)NE*BC*HID]; // 256 MB
__device__ float          g_eo[(size_t)NE*BC*DIMD];    // 64 MB expert outputs

// ---------------- zero scratch that is accumulated into (graph-captured) ----------------
__global__ __launch_bounds__(256) void zero_kernel()
{
    size_t i = (size_t)blockIdx.x * 256 + threadIdx.x;
    float4* p = (float4*)g_ei;
    const size_t n4 = (size_t)NE*BC*DIMD/4;
    const size_t stride = (size_t)gridDim.x * 256;
    float4 z = make_float4(0.f,0.f,0.f,0.f);
    for (size_t j = i; j < n4; j += stride) p[j] = z;
    if (blockIdx.x == 0 && threadIdx.x < NB*NE) g_proxy[threadIdx.x] = 0.f;
}

// ---------------- gating: logits -> softmax -> sort -> threshold-k ----------------
__global__ __launch_bounds__(256) void gating_kernel(const float* __restrict__ x,
                                                     const float* __restrict__ wg)
{
    __shared__ float s_wg[DIMD*NE];   // 32 KB
    __shared__ float s_proxy[NE];
    int tid = threadIdx.x;
    for (int i = tid; i < DIMD*NE; i += 256) s_wg[i] = wg[i];
    if (tid < NE) s_proxy[tid] = 0.f;
    __syncthreads();

    int warp = tid >> 5, lane = tid & 31;
    int t = blockIdx.x * 8 + warp;            // token id, 8 tokens/block
    const float* xr = x + (size_t)t * DIMD;

    float acc[NE];
    #pragma unroll
    for (int e = 0; e < NE; e++) acc[e] = 0.f;
    for (int d = lane; d < DIMD; d += 32) {
        float xv = xr[d];
        #pragma unroll
        for (int e = 0; e < NE; e++) acc[e] += xv * s_wg[d*NE + e];
    }
    #pragma unroll
    for (int e = 0; e < NE; e++) {
        #pragma unroll
        for (int off = 16; off; off >>= 1)
            acc[e] += __shfl_xor_sync(0xFFFFFFFFu, acc[e], off);
    }

    if (lane == 0) {
        // softmax (fp32, max-subtract)
        float mx = acc[0];
        #pragma unroll
        for (int e = 1; e < NE; e++) mx = fmaxf(mx, acc[e]);
        float p[NE]; float sum = 0.f;
        #pragma unroll
        for (int e = 0; e < NE; e++) { p[e] = expf(acc[e] - mx); sum += p[e]; }
        float inv = 1.f / sum;
        #pragma unroll
        for (int e = 0; e < NE; e++) p[e] *= inv;

        // stable descending insertion sort
        float sv[NE]; int si[NE];
        #pragma unroll
        for (int i = 0; i < NE; i++) { sv[i] = p[i]; si[i] = i; }
        for (int i = 1; i < NE; i++) {
            float key = sv[i]; int ki = si[i];
            int j = i - 1;
            while (j >= 0 && sv[j] < key) { sv[j+1] = sv[j]; si[j+1] = si[j]; j--; }
            sv[j+1] = key; si[j+1] = ki;
        }
        // threshold-k (cum >= 0.8)
        float cum = 0.f; int k = NE;
        for (int i = 0; i < NE; i++) {
            cum += sv[i];
            if (cum >= 0.8f) { k = i + 1; break; }
        }
        float denom = 0.f;
        for (int i = 0; i < k; i++) denom += sv[i];
        float invd = 1.f / denom;

        #pragma unroll
        for (int e = 0; e < NE; e++) { g_mask[t*NE+e] = 0; g_weights[t*NE+e] = 0.f; }
        for (int i = 0; i < k; i++) {
            g_mask[t*NE + si[i]]    = 1;
            g_weights[t*NE + si[i]] = sv[i] * invd;
        }
        #pragma unroll
        for (int e = 0; e < NE; e++) atomicAdd(&s_proxy[e], p[e]);
    }
    __syncthreads();
    if (tid < NE) {
        int b = (blockIdx.x * 8) / NN;
        atomicAdd(&g_proxy[b*NE + tid], s_proxy[tid]);
    }
}

// ---------------- capacity scan per (b,e): exclusive cumsum + truncate ----------------
__global__ void scan_kernel()
{
    int be = blockIdx.x;              // b*NE + e
    int b = be / NE, e = be % NE;
    int lane = threadIdx.x;
    int running = 0;
    for (int n0 = 0; n0 < NN; n0 += 32) {
        int t = b * NN + n0 + lane;
        int m = g_mask[t*NE + e];
        unsigned bal = __ballot_sync(0xFFFFFFFFu, m);
        int pos = running + __popc(bal & ((1u << lane) - 1u));
        int valid = m && (pos < CAP);
        g_mask[t*NE + e] = (unsigned char)valid;
        g_posE[t*NE + e] = valid ? pos : 0;
        running += __popc(bal);
    }
    if (lane == 0) g_density[be] = (float)min(running, CAP) / (float)NN;
}

__global__ void postok_kernel()
{
    int t = blockIdx.x * 256 + threadIdx.x;
    if (t >= NTOK) return;
    int s = 0;
    #pragma unroll
    for (int e = 0; e < NE; e++) s += g_posE[t*NE + e];
    g_postok[t] = s;
}

__global__ void loss_kernel(float* __restrict__ out, int out_size)
{
    int tid = threadIdx.x;   // 128 threads, one per (b,e)
    float v = (g_proxy[tid] * (1.0f / (float)NN)) * g_density[tid];
    #pragma unroll
    for (int off = 16; off; off >>= 1) v += __shfl_xor_sync(0xFFFFFFFFu, v, off);
    __shared__ float s[4];
    if ((tid & 31) == 0) s[tid >> 5] = v;
    __syncthreads();
    if (tid == 0) {
        float total = s[0] + s[1] + s[2] + s[3];
        float loss = total * (1.0f / 128.0f) * 256.0f * 0.01f;
        if (out_size > NTOK*DIMD) out[NTOK*DIMD] = loss;   // loss follows the [B,N,D] tensor
    }
}

// ---------------- dispatch scatter: ei[e, b*CAP+pt, :] += x[b,n,:] ----------------
__global__ __launch_bounds__(128) void scatter_kernel(const float* __restrict__ x)
{
    int t = blockIdx.x;
    int tid = threadIdx.x;            // 128 threads, float4 each
    int pt = g_postok[t];
    if (pt >= CAP) return;
    int b = t >> 11;                  // t / NN
    int row = b * CAP + pt;
    float4 xv = ((const float4*)(x + (size_t)t * DIMD))[tid];
    #pragma unroll
    for (int e = 0; e < NE; e++) {
        if (g_mask[t*NE + e]) {
            float* dst = g_ei + ((size_t)e * BC + row) * DIMD + tid * 4;
            atomicAdd(dst + 0, xv.x);
            atomicAdd(dst + 1, xv.y);
            atomicAdd(dst + 2, xv.z);
            atomicAdd(dst + 3, xv.w);
        }
    }
}

// ---------------- batched SGEMM: C[e] = (gelu?)(A[e] @ B[e]) ----------------
template<bool APPLY_GELU>
__global__ __launch_bounds__(256) void gemm_kernel(const float* __restrict__ Ag,
                                                   const float* __restrict__ Bg,
                                                   float* __restrict__ Cg,
                                                   int M, int N, int K)
{
    const float* A  = Ag + (size_t)blockIdx.z * M * K;
    const float* Bp = Bg + (size_t)blockIdx.z * K * N;
    float*       C  = Cg + (size_t)blockIdx.z * M * N;

    __shared__ float As[8][128];
    __shared__ float Bs[8][128];

    int tid = threadIdx.x;
    int tr = tid >> 4, tc = tid & 15;       // 16x16 thread grid, 8x8 each
    int aRow = tid >> 1;                    // 0..127
    int aCol = (tid & 1) * 4;               // 0 or 4
    int bRow = tid >> 5;                    // 0..7
    int bCol = (tid & 31) * 4;              // 0..124

    const float* Aptr = A + (size_t)(blockIdx.y * 128 + aRow) * K + aCol;
    const float* Bptr = Bp + (size_t)bRow * N + blockIdx.x * 128 + bCol;

    float acc[8][8];
    #pragma unroll
    for (int i = 0; i < 8; i++)
        #pragma unroll
        for (int j = 0; j < 8; j++) acc[i][j] = 0.f;

    for (int kt = 0; kt < K; kt += 8) {
        float4 av = *(const float4*)(Aptr + kt);
        float4 bv = *(const float4*)(Bptr + (size_t)kt * N);
        As[aCol + 0][aRow] = av.x;
        As[aCol + 1][aRow] = av.y;
        As[aCol + 2][aRow] = av.z;
        As[aCol + 3][aRow] = av.w;
        *(float4*)&Bs[bRow][bCol] = bv;
        __syncthreads();
        #pragma unroll
        for (int k = 0; k < 8; k++) {
            float ra[8], rb[8];
            *(float4*)&ra[0] = *(const float4*)&As[k][tr*8];
            *(float4*)&ra[4] = *(const float4*)&As[k][tr*8 + 4];
            *(float4*)&rb[0] = *(const float4*)&Bs[k][tc*8];
            *(float4*)&rb[4] = *(const float4*)&Bs[k][tc*8 + 4];
            #pragma unroll
            for (int i = 0; i < 8; i++)
                #pragma unroll
                for (int j = 0; j < 8; j++) acc[i][j] += ra[i] * rb[j];
        }
        __syncthreads();
    }

    #pragma unroll
    for (int i = 0; i < 8; i++) {
        int row = blockIdx.y * 128 + tr * 8 + i;
        float* crow = C + (size_t)row * N + blockIdx.x * 128 + tc * 8;
        float v[8];
        #pragma unroll
        for (int j = 0; j < 8; j++) {
            float z = acc[i][j];
            if (APPLY_GELU) z = 0.5f * z * (1.0f + erff(z * 0.70710678118654752f));
            v[j] = z;
        }
        *(float4*)crow       = make_float4(v[0], v[1], v[2], v[3]);
        *(float4*)(crow + 4) = make_float4(v[4], v[5], v[6], v[7]);
    }
}

// ---------------- combine: out[b,n,:] = sum_e w_e * eo[e, b*CAP+pt, :] ----------------
__global__ __launch_bounds__(128) void combine_kernel(float* __restrict__ out)
{
    int t = blockIdx.x;
    int tid = threadIdx.x;
    float4 acc = make_float4(0.f, 0.f, 0.f, 0.f);
    int pt = g_postok[t];
    if (pt < CAP) {
        int b = t >> 11;
        int row = b * CAP + pt;
        #pragma unroll
        for (int e = 0; e < NE; e++) {
            if (g_mask[t*NE + e]) {
                float w = g_weights[t*NE + e];
                float4 v = ((const float4*)(g_eo + ((size_t)e * BC + row) * DIMD))[tid];
                acc.x += w * v.x; acc.y += w * v.y; acc.z += w * v.z; acc.w += w * v.w;
            }
        }
    }
    ((float4*)(out + (size_t)t * DIMD))[tid] = acc;
}

// ---------------- launch ----------------
extern "C" void kernel_launch(void* const* d_in, const int* in_sizes, int n_in,
                              void* d_out, int out_size)
{
    // Identify inputs BY SIZE (robust to metadata ordering):
    //   x: B*N*D = 8,388,608   w_gating: D*E = 8,192   w1/w2: E*D*H = 16,777,216 (w1 first)
    const float* x  = nullptr;
    const float* wg = nullptr;
    const float* w1 = nullptr;
    const float* w2 = nullptr;
    for (int i = 0; i < n_in; i++) {
        int sz = in_sizes[i];
        const float* p = (const float*)d_in[i];
        if (sz == NTOK*DIMD)            { x = p; }
        else if (sz == DIMD*NE)         { wg = p; }
        else if (sz == NE*DIMD*HID)     { if (!w1) w1 = p; else w2 = p; }
    }
    if (!x || !wg || !w1 || !w2) {      // fallback to declared order
        x  = (const float*)d_in[0];
        wg = (const float*)d_in[1];
        w1 = (const float*)d_in[2];
        w2 = (const float*)d_in[3];
    }
    float* out = (float*)d_out;

    // CRITICAL FIX: __device__ symbols cannot be passed from host code directly —
    // that passes the host shadow address. Resolve true device pointers.
    static float* p_ei = nullptr;
    static float* p_hidden = nullptr;
    static float* p_eo = nullptr;
    if (!p_ei) {
        cudaGetSymbolAddress((void**)&p_ei,     g_ei);
        cudaGetSymbolAddress((void**)&p_hidden, g_hidden);
        cudaGetSymbolAddress((void**)&p_eo,     g_eo);
    }

    zero_kernel<<<2048, 256>>>();                 // zero g_ei + g_proxy (graph-captured)
    gating_kernel<<<NTOK/8, 256>>>(x, wg);
    scan_kernel<<<NB*NE, 32>>>();
    postok_kernel<<<NTOK/256, 256>>>();
    loss_kernel<<<1, 128>>>(out, out_size);
    scatter_kernel<<<NTOK, 128>>>(x);

    // GEMM1 + GELU: [BC x DIMD] @ [DIMD x HID] per expert
    gemm_kernel<true ><<<dim3(HID/128, BC/128, NE), 256>>>(p_ei, w1, p_hidden, BC, HID, DIMD);
    // GEMM2: [BC x HID] @ [HID x DIMD] per expert
    gemm_kernel<false><<<dim3(DIMD/128, BC/128, NE), 256>>>(p_hidden, w2, p_eo, BC, DIMD, HID);

    combine_kernel<<<NTOK, 128>>>(out);
}

// round 6
// speedup vs baseline: 1.9522x; 1.9522x over previous
#include <cuda_runtime.h>
#include <math.h>
#include <stdint.h>

#define DIMD 512
#define HID  2048
#define NE   16
#define NB   8
#define NN   2048
#define CAP  256
#define NTOK (NB*NN)          // 16384
#define BC   (NB*CAP)         // 2048 rows per expert

// ---------------- device scratch (no allocations allowed) ----------------
__device__ float          g_weights[NTOK*NE];
__device__ unsigned char  g_mask[NTOK*NE];
__device__ int            g_posE[NTOK*NE];
__device__ int            g_postok[NTOK];
__device__ float          g_proxy[NB*NE];
__device__ float          g_density[NB*NE];
__device__ float          g_ei[(size_t)NE*BC*DIMD];    // 64 MB expert inputs
__device__ float          g_hidden[(size_t)NE*BC*HID]; // 256 MB
__device__ float          g_eo[(size_t)NE*BC*DIMD];    // 64 MB expert outputs

// ---------------- zero scratch (graph-captured) ----------------
__global__ __launch_bounds__(256) void zero_kernel()
{
    size_t i = (size_t)blockIdx.x * 256 + threadIdx.x;
    float4* p = (float4*)g_ei;
    const size_t n4 = (size_t)NE*BC*DIMD/4;
    const size_t stride = (size_t)gridDim.x * 256;
    float4 z = make_float4(0.f,0.f,0.f,0.f);
    for (size_t j = i; j < n4; j += stride) p[j] = z;
    if (blockIdx.x == 0 && threadIdx.x < NB*NE) g_proxy[threadIdx.x] = 0.f;
}

// ---------------- gating ----------------
__global__ __launch_bounds__(256) void gating_kernel(const float* __restrict__ x,
                                                     const float* __restrict__ wg)
{
    __shared__ float s_wg[DIMD*NE];
    __shared__ float s_proxy[NE];
    int tid = threadIdx.x;
    for (int i = tid; i < DIMD*NE; i += 256) s_wg[i] = wg[i];
    if (tid < NE) s_proxy[tid] = 0.f;
    __syncthreads();

    int warp = tid >> 5, lane = tid & 31;
    int t = blockIdx.x * 8 + warp;
    const float* xr = x + (size_t)t * DIMD;

    float acc[NE];
    #pragma unroll
    for (int e = 0; e < NE; e++) acc[e] = 0.f;
    for (int d = lane; d < DIMD; d += 32) {
        float xv = xr[d];
        #pragma unroll
        for (int e = 0; e < NE; e++) acc[e] += xv * s_wg[d*NE + e];
    }
    #pragma unroll
    for (int e = 0; e < NE; e++) {
        #pragma unroll
        for (int off = 16; off; off >>= 1)
            acc[e] += __shfl_xor_sync(0xFFFFFFFFu, acc[e], off);
    }

    if (lane == 0) {
        float mx = acc[0];
        #pragma unroll
        for (int e = 1; e < NE; e++) mx = fmaxf(mx, acc[e]);
        float p[NE]; float sum = 0.f;
        #pragma unroll
        for (int e = 0; e < NE; e++) { p[e] = expf(acc[e] - mx); sum += p[e]; }
        float inv = 1.f / sum;
        #pragma unroll
        for (int e = 0; e < NE; e++) p[e] *= inv;

        float sv[NE]; int si[NE];
        #pragma unroll
        for (int i = 0; i < NE; i++) { sv[i] = p[i]; si[i] = i; }
        for (int i = 1; i < NE; i++) {
            float key = sv[i]; int ki = si[i];
            int j = i - 1;
            while (j >= 0 && sv[j] < key) { sv[j+1] = sv[j]; si[j+1] = si[j]; j--; }
            sv[j+1] = key; si[j+1] = ki;
        }
        float cum = 0.f; int k = NE;
        for (int i = 0; i < NE; i++) {
            cum += sv[i];
            if (cum >= 0.8f) { k = i + 1; break; }
        }
        float denom = 0.f;
        for (int i = 0; i < k; i++) denom += sv[i];
        float invd = 1.f / denom;

        #pragma unroll
        for (int e = 0; e < NE; e++) { g_mask[t*NE+e] = 0; g_weights[t*NE+e] = 0.f; }
        for (int i = 0; i < k; i++) {
            g_mask[t*NE + si[i]]    = 1;
            g_weights[t*NE + si[i]] = sv[i] * invd;
        }
        #pragma unroll
        for (int e = 0; e < NE; e++) atomicAdd(&s_proxy[e], p[e]);
    }
    __syncthreads();
    if (tid < NE) {
        int b = (blockIdx.x * 8) / NN;
        atomicAdd(&g_proxy[b*NE + tid], s_proxy[tid]);
    }
}

// ---------------- capacity scan ----------------
__global__ void scan_kernel()
{
    int be = blockIdx.x;
    int b = be / NE, e = be % NE;
    int lane = threadIdx.x;
    int running = 0;
    for (int n0 = 0; n0 < NN; n0 += 32) {
        int t = b * NN + n0 + lane;
        int m = g_mask[t*NE + e];
        unsigned bal = __ballot_sync(0xFFFFFFFFu, m);
        int pos = running + __popc(bal & ((1u << lane) - 1u));
        int valid = m && (pos < CAP);
        g_mask[t*NE + e] = (unsigned char)valid;
        g_posE[t*NE + e] = valid ? pos : 0;
        running += __popc(bal);
    }
    if (lane == 0) g_density[be] = (float)min(running, CAP) / (float)NN;
}

__global__ void postok_kernel()
{
    int t = blockIdx.x * 256 + threadIdx.x;
    if (t >= NTOK) return;
    int s = 0;
    #pragma unroll
    for (int e = 0; e < NE; e++) s += g_posE[t*NE + e];
    g_postok[t] = s;
}

__global__ void loss_kernel(float* __restrict__ out, int out_size)
{
    int tid = threadIdx.x;
    float v = (g_proxy[tid] * (1.0f / (float)NN)) * g_density[tid];
    #pragma unroll
    for (int off = 16; off; off >>= 1) v += __shfl_xor_sync(0xFFFFFFFFu, v, off);
    __shared__ float s[4];
    if ((tid & 31) == 0) s[tid >> 5] = v;
    __syncthreads();
    if (tid == 0) {
        float total = s[0] + s[1] + s[2] + s[3];
        float loss = total * (1.0f / 128.0f) * 256.0f * 0.01f;
        if (out_size > NTOK*DIMD) out[NTOK*DIMD] = loss;
    }
}

// ---------------- dispatch scatter ----------------
__global__ __launch_bounds__(128) void scatter_kernel(const float* __restrict__ x)
{
    int t = blockIdx.x;
    int tid = threadIdx.x;
    int pt = g_postok[t];
    if (pt >= CAP) return;
    int b = t >> 11;
    int row = b * CAP + pt;
    float4 xv = ((const float4*)(x + (size_t)t * DIMD))[tid];
    #pragma unroll
    for (int e = 0; e < NE; e++) {
        if (g_mask[t*NE + e]) {
            float* dst = g_ei + ((size_t)e * BC + row) * DIMD + tid * 4;
            atomicAdd(dst + 0, xv.x);
            atomicAdd(dst + 1, xv.y);
            atomicAdd(dst + 2, xv.z);
            atomicAdd(dst + 3, xv.w);
        }
    }
}

// ---------------- tf32 tensor-core batched GEMM ----------------
// C[e] = (gelu?)(A[e] @ B[e]);  A: MxK row-major, B: KxN row-major.
// Block tile 128x128, BK=32, 8 warps (2m x 4n), warp tile 64x32, mma m16n8k8.

__device__ __forceinline__ uint32_t f2tf32(float f)
{
    uint32_t u;
    asm("cvt.rna.tf32.f32 %0, %1;" : "=r"(u) : "f"(f));
    return u;
}

__device__ __forceinline__ void mma_16x8x8(float c[4], const uint32_t a[4], const uint32_t b[2])
{
    asm volatile(
        "mma.sync.aligned.m16n8k8.row.col.f32.tf32.tf32.f32 "
        "{%0,%1,%2,%3}, {%4,%5,%6,%7}, {%8,%9}, {%0,%1,%2,%3};\n"
        : "+f"(c[0]), "+f"(c[1]), "+f"(c[2]), "+f"(c[3])
        : "r"(a[0]), "r"(a[1]), "r"(a[2]), "r"(a[3]), "r"(b[0]), "r"(b[1]));
}

template<bool APPLY_GELU>
__global__ __launch_bounds__(256) void gemm_tf32_kernel(const float* __restrict__ Ag,
                                                        const float* __restrict__ Bg,
                                                        float* __restrict__ Cg,
                                                        int M, int N, int K)
{
    const float* A  = Ag + (size_t)blockIdx.z * M * K;
    const float* Bp = Bg + (size_t)blockIdx.z * K * N;
    float*       C  = Cg + (size_t)blockIdx.z * M * N;

    // k-major smem tiles, padded to 136 words/row -> conflict-free frag loads
    __shared__ uint32_t As[32][136];   // A^T tile: As[k][m]
    __shared__ uint32_t Bs[32][136];   // B tile:   Bs[k][n]

    const int tid  = threadIdx.x;
    const int warp = tid >> 5, lane = tid & 31;
    const int wm = (warp & 1) * 64;          // warp m-offset in block tile
    const int wn = (warp >> 1) * 32;         // warp n-offset
    const int g  = lane >> 2, tg = lane & 3; // groupID / threadID_in_group

    const int bm = blockIdx.y * 128;
    const int bn = blockIdx.x * 128;

    // global-load assignments
    const int aRow = tid >> 1;               // 0..127
    const int aCol = (tid & 1) * 16;         // 0 or 16
    const int bRow = tid >> 3;               // 0..31
    const int bCol = (tid & 7) * 16;         // 0..112

    const float* aptr = A + (size_t)(bm + aRow) * K + aCol;
    const float* bptr = Bp + (size_t)bRow * N + bn + bCol;

    float c[4][4][4];                        // [mf][nf][reg]
    #pragma unroll
    for (int mf = 0; mf < 4; mf++)
        #pragma unroll
        for (int nf = 0; nf < 4; nf++)
            #pragma unroll
            for (int r = 0; r < 4; r++) c[mf][nf][r] = 0.f;

    for (int kt = 0; kt < K; kt += 32) {
        // A: 16 contiguous floats/thread, transpose into As[k][m]
        {
            const float4* p4 = (const float4*)(aptr + kt);
            #pragma unroll
            for (int v = 0; v < 4; v++) {
                float4 av = p4[v];
                As[aCol + v*4 + 0][aRow] = f2tf32(av.x);
                As[aCol + v*4 + 1][aRow] = f2tf32(av.y);
                As[aCol + v*4 + 2][aRow] = f2tf32(av.z);
                As[aCol + v*4 + 3][aRow] = f2tf32(av.w);
            }
        }
        // B: 16 contiguous floats/thread, direct into Bs[k][n]
        {
            const float4* p4 = (const float4*)(bptr + (size_t)kt * N);
            #pragma unroll
            for (int v = 0; v < 4; v++) {
                float4 bv = p4[v];
                uint4 w;
                w.x = f2tf32(bv.x); w.y = f2tf32(bv.y);
                w.z = f2tf32(bv.z); w.w = f2tf32(bv.w);
                *(uint4*)&Bs[bRow][bCol + v*4] = w;
            }
        }
        __syncthreads();

        #pragma unroll
        for (int ks = 0; ks < 4; ks++) {
            const int k = ks * 8;
            uint32_t af[4][4];
            #pragma unroll
            for (int mf = 0; mf < 4; mf++) {
                const int m = wm + mf*16 + g;
                af[mf][0] = As[k + tg    ][m];
                af[mf][1] = As[k + tg    ][m + 8];
                af[mf][2] = As[k + tg + 4][m];
                af[mf][3] = As[k + tg + 4][m + 8];
            }
            uint32_t bf[4][2];
            #pragma unroll
            for (int nf = 0; nf < 4; nf++) {
                const int n = wn + nf*8 + g;
                bf[nf][0] = Bs[k + tg    ][n];
                bf[nf][1] = Bs[k + tg + 4][n];
            }
            #pragma unroll
            for (int mf = 0; mf < 4; mf++)
                #pragma unroll
                for (int nf = 0; nf < 4; nf++)
                    mma_16x8x8(c[mf][nf], af[mf], bf[nf]);
        }
        __syncthreads();
    }

    // epilogue
    #pragma unroll
    for (int mf = 0; mf < 4; mf++) {
        const int row0 = bm + wm + mf*16 + g;
        #pragma unroll
        for (int nf = 0; nf < 4; nf++) {
            const int col = bn + wn + nf*8 + 2*tg;
            float v[4];
            #pragma unroll
            for (int r = 0; r < 4; r++) {
                float z = c[mf][nf][r];
                if (APPLY_GELU) z = 0.5f * z * (1.0f + erff(z * 0.70710678118654752f));
                v[r] = z;
            }
            *(float2*)(C + (size_t)row0       * N + col) = make_float2(v[0], v[1]);
            *(float2*)(C + (size_t)(row0 + 8) * N + col) = make_float2(v[2], v[3]);
        }
    }
}

// ---------------- combine ----------------
__global__ __launch_bounds__(128) void combine_kernel(float* __restrict__ out)
{
    int t = blockIdx.x;
    int tid = threadIdx.x;
    float4 acc = make_float4(0.f, 0.f, 0.f, 0.f);
    int pt = g_postok[t];
    if (pt < CAP) {
        int b = t >> 11;
        int row = b * CAP + pt;
        #pragma unroll
        for (int e = 0; e < NE; e++) {
            if (g_mask[t*NE + e]) {
                float w = g_weights[t*NE + e];
                float4 v = ((const float4*)(g_eo + ((size_t)e * BC + row) * DIMD))[tid];
                acc.x += w * v.x; acc.y += w * v.y; acc.z += w * v.z; acc.w += w * v.w;
            }
        }
    }
    ((float4*)(out + (size_t)t * DIMD))[tid] = acc;
}

// ---------------- launch ----------------
extern "C" void kernel_launch(void* const* d_in, const int* in_sizes, int n_in,
                              void* d_out, int out_size)
{
    const float* x  = nullptr;
    const float* wg = nullptr;
    const float* w1 = nullptr;
    const float* w2 = nullptr;
    for (int i = 0; i < n_in; i++) {
        int sz = in_sizes[i];
        const float* p = (const float*)d_in[i];
        if (sz == NTOK*DIMD)            { x = p; }
        else if (sz == DIMD*NE)         { wg = p; }
        else if (sz == NE*DIMD*HID)     { if (!w1) w1 = p; else w2 = p; }
    }
    if (!x || !wg || !w1 || !w2) {
        x  = (const float*)d_in[0];
        wg = (const float*)d_in[1];
        w1 = (const float*)d_in[2];
        w2 = (const float*)d_in[3];
    }
    float* out = (float*)d_out;

    // __device__ symbols must be resolved to real device addresses for host-side args
    static float* p_ei = nullptr;
    static float* p_hidden = nullptr;
    static float* p_eo = nullptr;
    if (!p_ei) {
        cudaGetSymbolAddress((void**)&p_ei,     g_ei);
        cudaGetSymbolAddress((void**)&p_hidden, g_hidden);
        cudaGetSymbolAddress((void**)&p_eo,     g_eo);
    }

    zero_kernel<<<2048, 256>>>();
    gating_kernel<<<NTOK/8, 256>>>(x, wg);
    scan_kernel<<<NB*NE, 32>>>();
    postok_kernel<<<NTOK/256, 256>>>();
    loss_kernel<<<1, 128>>>(out, out_size);
    scatter_kernel<<<NTOK, 128>>>(x);

    // GEMM1 + GELU: [BC x DIMD] @ [DIMD x HID] per expert
    gemm_tf32_kernel<true ><<<dim3(HID/128, BC/128, NE), 256>>>(p_ei, w1, p_hidden, BC, HID, DIMD);
    // GEMM2: [BC x HID] @ [HID x DIMD] per expert
    gemm_tf32_kernel<false><<<dim3(DIMD/128, BC/128, NE), 256>>>(p_hidden, w2, p_eo, BC, DIMD, HID);

    combine_kernel<<<NTOK, 128>>>(out);
}

// round 7
// speedup vs baseline: 2.2470x; 1.1510x over previous
#include <cuda_runtime.h>
#include <math.h>
#include <stdint.h>

#define DIMD 512
#define HID  2048
#define NE   16
#define NB   8
#define NN   2048
#define CAP  256
#define NTOK (NB*NN)          // 16384
#define BC   (NB*CAP)         // 2048 rows per expert

// ---------------- device scratch ----------------
__device__ float          g_weights[NTOK*NE];
__device__ unsigned char  g_mask[NTOK*NE];
__device__ int            g_posE[NTOK*NE];
__device__ int            g_postok[NTOK];
__device__ float          g_proxy[NB*NE];
__device__ float          g_density[NB*NE];
__device__ float          g_ei[(size_t)NE*BC*DIMD];    // 64 MB
__device__ float          g_hidden[(size_t)NE*BC*HID]; // 256 MB
__device__ float          g_eo[(size_t)NE*BC*DIMD];    // 64 MB

// ---------------- zero scratch ----------------
__global__ __launch_bounds__(256) void zero_kernel()
{
    size_t i = (size_t)blockIdx.x * 256 + threadIdx.x;
    float4* p = (float4*)g_ei;
    const size_t n4 = (size_t)NE*BC*DIMD/4;
    const size_t stride = (size_t)gridDim.x * 256;
    float4 z = make_float4(0.f,0.f,0.f,0.f);
    for (size_t j = i; j < n4; j += stride) p[j] = z;
    if (blockIdx.x == 0 && threadIdx.x < NB*NE) g_proxy[threadIdx.x] = 0.f;
}

// ---------------- gating ----------------
__global__ __launch_bounds__(256) void gating_kernel(const float* __restrict__ x,
                                                     const float* __restrict__ wg)
{
    __shared__ float s_wg[DIMD*NE];
    __shared__ float s_proxy[NE];
    int tid = threadIdx.x;
    for (int i = tid; i < DIMD*NE; i += 256) s_wg[i] = wg[i];
    if (tid < NE) s_proxy[tid] = 0.f;
    __syncthreads();

    int warp = tid >> 5, lane = tid & 31;
    int t = blockIdx.x * 8 + warp;
    const float* xr = x + (size_t)t * DIMD;

    float acc[NE];
    #pragma unroll
    for (int e = 0; e < NE; e++) acc[e] = 0.f;
    for (int d = lane; d < DIMD; d += 32) {
        float xv = xr[d];
        #pragma unroll
        for (int e = 0; e < NE; e++) acc[e] += xv * s_wg[d*NE + e];
    }
    #pragma unroll
    for (int e = 0; e < NE; e++) {
        #pragma unroll
        for (int off = 16; off; off >>= 1)
            acc[e] += __shfl_xor_sync(0xFFFFFFFFu, acc[e], off);
    }

    if (lane == 0) {
        float mx = acc[0];
        #pragma unroll
        for (int e = 1; e < NE; e++) mx = fmaxf(mx, acc[e]);
        float p[NE]; float sum = 0.f;
        #pragma unroll
        for (int e = 0; e < NE; e++) { p[e] = expf(acc[e] - mx); sum += p[e]; }
        float inv = 1.f / sum;
        #pragma unroll
        for (int e = 0; e < NE; e++) p[e] *= inv;

        float sv[NE]; int si[NE];
        #pragma unroll
        for (int i = 0; i < NE; i++) { sv[i] = p[i]; si[i] = i; }
        for (int i = 1; i < NE; i++) {
            float key = sv[i]; int ki = si[i];
            int j = i - 1;
            while (j >= 0 && sv[j] < key) { sv[j+1] = sv[j]; si[j+1] = si[j]; j--; }
            sv[j+1] = key; si[j+1] = ki;
        }
        float cum = 0.f; int k = NE;
        for (int i = 0; i < NE; i++) {
            cum += sv[i];
            if (cum >= 0.8f) { k = i + 1; break; }
        }
        float denom = 0.f;
        for (int i = 0; i < k; i++) denom += sv[i];
        float invd = 1.f / denom;

        #pragma unroll
        for (int e = 0; e < NE; e++) { g_mask[t*NE+e] = 0; g_weights[t*NE+e] = 0.f; }
        for (int i = 0; i < k; i++) {
            g_mask[t*NE + si[i]]    = 1;
            g_weights[t*NE + si[i]] = sv[i] * invd;
        }
        #pragma unroll
        for (int e = 0; e < NE; e++) atomicAdd(&s_proxy[e], p[e]);
    }
    __syncthreads();
    if (tid < NE) {
        int b = (blockIdx.x * 8) / NN;
        atomicAdd(&g_proxy[b*NE + tid], s_proxy[tid]);
    }
}

// ---------------- capacity scan ----------------
__global__ void scan_kernel()
{
    int be = blockIdx.x;
    int b = be / NE, e = be % NE;
    int lane = threadIdx.x;
    int running = 0;
    for (int n0 = 0; n0 < NN; n0 += 32) {
        int t = b * NN + n0 + lane;
        int m = g_mask[t*NE + e];
        unsigned bal = __ballot_sync(0xFFFFFFFFu, m);
        int pos = running + __popc(bal & ((1u << lane) - 1u));
        int valid = m && (pos < CAP);
        g_mask[t*NE + e] = (unsigned char)valid;
        g_posE[t*NE + e] = valid ? pos : 0;
        running += __popc(bal);
    }
    if (lane == 0) g_density[be] = (float)min(running, CAP) / (float)NN;
}

__global__ void postok_kernel()
{
    int t = blockIdx.x * 256 + threadIdx.x;
    if (t >= NTOK) return;
    int s = 0;
    #pragma unroll
    for (int e = 0; e < NE; e++) s += g_posE[t*NE + e];
    g_postok[t] = s;
}

__global__ void loss_kernel(float* __restrict__ out, int out_size)
{
    int tid = threadIdx.x;
    float v = (g_proxy[tid] * (1.0f / (float)NN)) * g_density[tid];
    #pragma unroll
    for (int off = 16; off; off >>= 1) v += __shfl_xor_sync(0xFFFFFFFFu, v, off);
    __shared__ float s[4];
    if ((tid & 31) == 0) s[tid >> 5] = v;
    __syncthreads();
    if (tid == 0) {
        float total = s[0] + s[1] + s[2] + s[3];
        float loss = total * (1.0f / 128.0f) * 256.0f * 0.01f;
        if (out_size > NTOK*DIMD) out[NTOK*DIMD] = loss;
    }
}

// ---------------- dispatch scatter ----------------
__global__ __launch_bounds__(128) void scatter_kernel(const float* __restrict__ x)
{
    int t = blockIdx.x;
    int tid = threadIdx.x;
    int pt = g_postok[t];
    if (pt >= CAP) return;
    int b = t >> 11;
    int row = b * CAP + pt;
    float4 xv = ((const float4*)(x + (size_t)t * DIMD))[tid];
    #pragma unroll
    for (int e = 0; e < NE; e++) {
        if (g_mask[t*NE + e]) {
            float* dst = g_ei + ((size_t)e * BC + row) * DIMD + tid * 4;
            atomicAdd(dst + 0, xv.x);
            atomicAdd(dst + 1, xv.y);
            atomicAdd(dst + 2, xv.z);
            atomicAdd(dst + 3, xv.w);
        }
    }
}

// ---------------- tf32 tensor-core batched GEMM, cp.async double-buffered ----------
// C[e] = (gelu?)(A[e] @ B[e]);  A: MxK row-major, B: KxN row-major.
// Block tile 128x128, BK=32, 8 warps (2m x 4n), warp tile 64x32, mma m16n8k8.

#define AS_STRIDE 36      // 32 + 4 pad (floats)
#define BS_STRIDE 136     // 128 + 8 pad (floats)
#define AS_TILE (128*AS_STRIDE)
#define BS_TILE (32*BS_STRIDE)
#define GEMM_SMEM_BYTES ((2*AS_TILE + 2*BS_TILE)*4)

__device__ __forceinline__ uint32_t f2tf32(float f)
{
    uint32_t u;
    asm("cvt.rna.tf32.f32 %0, %1;" : "=r"(u) : "f"(f));
    return u;
}

__device__ __forceinline__ void cp_async16(uint32_t smem_addr, const void* gptr)
{
    asm volatile("cp.async.cg.shared.global [%0], [%1], 16;\n"
                 :: "r"(smem_addr), "l"(gptr));
}
__device__ __forceinline__ void cp_commit()
{
    asm volatile("cp.async.commit_group;\n" ::: "memory");
}
__device__ __forceinline__ void cp_wait1()
{
    asm volatile("cp.async.wait_group 1;\n" ::: "memory");
}

__device__ __forceinline__ void mma_16x8x8(float c[4], const uint32_t a[4], const uint32_t b[2])
{
    asm volatile(
        "mma.sync.aligned.m16n8k8.row.col.f32.tf32.tf32.f32 "
        "{%0,%1,%2,%3}, {%4,%5,%6,%7}, {%8,%9}, {%0,%1,%2,%3};\n"
        : "+f"(c[0]), "+f"(c[1]), "+f"(c[2]), "+f"(c[3])
        : "r"(a[0]), "r"(a[1]), "r"(a[2]), "r"(a[3]), "r"(b[0]), "r"(b[1]));
}

template<bool APPLY_GELU>
__global__ __launch_bounds__(256) void gemm_tf32_db_kernel(const float* __restrict__ Ag,
                                                           const float* __restrict__ Bg,
                                                           float* __restrict__ Cg,
                                                           int M, int N, int K)
{
    extern __shared__ float smem[];
    float* As = smem;                    // [2][128][AS_STRIDE]  (A tile [m][k])
    float* Bs = smem + 2*AS_TILE;        // [2][32][BS_STRIDE]   (B tile [k][n])

    const float* A  = Ag + (size_t)blockIdx.z * M * K;
    const float* Bp = Bg + (size_t)blockIdx.z * K * N;
    float*       C  = Cg + (size_t)blockIdx.z * M * N;

    const int tid  = threadIdx.x;
    const int warp = tid >> 5, lane = tid & 31;
    const int wm = (warp & 1) * 64;
    const int wn = (warp >> 1) * 32;
    const int g  = lane >> 2, tg = lane & 3;

    const int bm = blockIdx.y * 128;
    const int bn = blockIdx.x * 128;

    // cp.async thread assignments (each thread copies 4 float4s per tile)
    const int aRow = tid >> 1;                 // 0..127
    const int aCol = (tid & 1) * 16;           // 0 or 16
    const int bRow = tid >> 3;                 // 0..31
    const int bCol = (tid & 7) * 16;           // 0..112

    const float* aSrc = A  + (size_t)(bm + aRow) * K + aCol;     // + kt
    const float* bSrc = Bp + (size_t)bRow * N + bn + bCol;       // + kt*N

    const uint32_t asBase = (uint32_t)__cvta_generic_to_shared(As);
    const uint32_t bsBase = (uint32_t)__cvta_generic_to_shared(Bs);
    const uint32_t aDst = asBase + (aRow*AS_STRIDE + aCol)*4;    // + stage*AS_TILE*4 + v*16
    const uint32_t bDst = bsBase + (bRow*BS_STRIDE + bCol)*4;

    float c[4][4][4];
    #pragma unroll
    for (int mf = 0; mf < 4; mf++)
        #pragma unroll
        for (int nf = 0; nf < 4; nf++)
            #pragma unroll
            for (int r = 0; r < 4; r++) c[mf][nf][r] = 0.f;

    const int NT = K >> 5;   // K/32 tiles

    // prefetch tile 0 into stage 0
    #pragma unroll
    for (int v = 0; v < 4; v++) {
        cp_async16(aDst + v*16, aSrc + v*4);
        cp_async16(bDst + v*16, bSrc + v*4);
    }
    cp_commit();

    for (int it = 0; it < NT; it++) {
        const int stage = it & 1;
        // issue next tile into the other stage
        if (it + 1 < NT) {
            const int nstage = stage ^ 1;
            const int kt = (it + 1) << 5;
            const uint32_t aD = aDst + nstage*AS_TILE*4;
            const uint32_t bD = bDst + nstage*BS_TILE*4;
            const float* aS = aSrc + kt;
            const float* bS = bSrc + (size_t)kt * N;
            #pragma unroll
            for (int v = 0; v < 4; v++) {
                cp_async16(aD + v*16, aS + v*4);
                cp_async16(bD + v*16, bS + v*4);
            }
        }
        cp_commit();
        cp_wait1();              // current tile resident
        __syncthreads();

        const float* Asr = As + stage*AS_TILE;
        const float* Bsr = Bs + stage*BS_TILE;

        #pragma unroll
        for (int ks = 0; ks < 4; ks++) {
            const int k0 = ks * 8;
            uint32_t af[4][4];
            #pragma unroll
            for (int mf = 0; mf < 4; mf++) {
                const int m = wm + mf*16 + g;
                af[mf][0] = f2tf32(Asr[(m    )*AS_STRIDE + k0 + tg    ]);
                af[mf][1] = f2tf32(Asr[(m + 8)*AS_STRIDE + k0 + tg    ]);
                af[mf][2] = f2tf32(Asr[(m    )*AS_STRIDE + k0 + tg + 4]);
                af[mf][3] = f2tf32(Asr[(m + 8)*AS_STRIDE + k0 + tg + 4]);
            }
            uint32_t bf[4][2];
            #pragma unroll
            for (int nf = 0; nf < 4; nf++) {
                const int n = wn + nf*8 + g;
                bf[nf][0] = f2tf32(Bsr[(k0 + tg    )*BS_STRIDE + n]);
                bf[nf][1] = f2tf32(Bsr[(k0 + tg + 4)*BS_STRIDE + n]);
            }
            #pragma unroll
            for (int mf = 0; mf < 4; mf++)
                #pragma unroll
                for (int nf = 0; nf < 4; nf++)
                    mma_16x8x8(c[mf][nf], af[mf], bf[nf]);
        }
        __syncthreads();
    }

    // epilogue
    #pragma unroll
    for (int mf = 0; mf < 4; mf++) {
        const int row0 = bm + wm + mf*16 + g;
        #pragma unroll
        for (int nf = 0; nf < 4; nf++) {
            const int col = bn + wn + nf*8 + 2*tg;
            float v[4];
            #pragma unroll
            for (int r = 0; r < 4; r++) {
                float z = c[mf][nf][r];
                if (APPLY_GELU) z = 0.5f * z * (1.0f + erff(z * 0.70710678118654752f));
                v[r] = z;
            }
            *(float2*)(C + (size_t)row0       * N + col) = make_float2(v[0], v[1]);
            *(float2*)(C + (size_t)(row0 + 8) * N + col) = make_float2(v[2], v[3]);
        }
    }
}

// ---------------- combine ----------------
__global__ __launch_bounds__(128) void combine_kernel(float* __restrict__ out)
{
    int t = blockIdx.x;
    int tid = threadIdx.x;
    float4 acc = make_float4(0.f, 0.f, 0.f, 0.f);
    int pt = g_postok[t];
    if (pt < CAP) {
        int b = t >> 11;
        int row = b * CAP + pt;
        #pragma unroll
        for (int e = 0; e < NE; e++) {
            if (g_mask[t*NE + e]) {
                float w = g_weights[t*NE + e];
                float4 v = ((const float4*)(g_eo + ((size_t)e * BC + row) * DIMD))[tid];
                acc.x += w * v.x; acc.y += w * v.y; acc.z += w * v.z; acc.w += w * v.w;
            }
        }
    }
    ((float4*)(out + (size_t)t * DIMD))[tid] = acc;
}

// ---------------- launch ----------------
extern "C" void kernel_launch(void* const* d_in, const int* in_sizes, int n_in,
                              void* d_out, int out_size)
{
    const float* x  = nullptr;
    const float* wg = nullptr;
    const float* w1 = nullptr;
    const float* w2 = nullptr;
    for (int i = 0; i < n_in; i++) {
        int sz = in_sizes[i];
        const float* p = (const float*)d_in[i];
        if (sz == NTOK*DIMD)            { x = p; }
        else if (sz == DIMD*NE)         { wg = p; }
        else if (sz == NE*DIMD*HID)     { if (!w1) w1 = p; else w2 = p; }
    }
    if (!x || !wg || !w1 || !w2) {
        x  = (const float*)d_in[0];
        wg = (const float*)d_in[1];
        w1 = (const float*)d_in[2];
        w2 = (const float*)d_in[3];
    }
    float* out = (float*)d_out;

    static float* p_ei = nullptr;
    static float* p_hidden = nullptr;
    static float* p_eo = nullptr;
    if (!p_ei) {
        cudaGetSymbolAddress((void**)&p_ei,     g_ei);
        cudaGetSymbolAddress((void**)&p_hidden, g_hidden);
        cudaGetSymbolAddress((void**)&p_eo,     g_eo);
        cudaFuncSetAttribute(gemm_tf32_db_kernel<true>,
                             cudaFuncAttributeMaxDynamicSharedMemorySize, GEMM_SMEM_BYTES);
        cudaFuncSetAttribute(gemm_tf32_db_kernel<false>,
                             cudaFuncAttributeMaxDynamicSharedMemorySize, GEMM_SMEM_BYTES);
    }

    zero_kernel<<<2048, 256>>>();
    gating_kernel<<<NTOK/8, 256>>>(x, wg);
    scan_kernel<<<NB*NE, 32>>>();
    postok_kernel<<<NTOK/256, 256>>>();
    loss_kernel<<<1, 128>>>(out, out_size);
    scatter_kernel<<<NTOK, 128>>>(x);

    // GEMM1 + GELU: [BC x DIMD] @ [DIMD x HID] per expert
    gemm_tf32_db_kernel<true ><<<dim3(HID/128, BC/128, NE), 256, GEMM_SMEM_BYTES>>>(p_ei, w1, p_hidden, BC, HID, DIMD);
    // GEMM2: [BC x HID] @ [HID x DIMD] per expert
    gemm_tf32_db_kernel<false><<<dim3(DIMD/128, BC/128, NE), 256, GEMM_SMEM_BYTES>>>(p_hidden, w2, p_eo, BC, DIMD, HID);

    combine_kernel<<<NTOK, 128>>>(out);
}